// round 16
// baseline (speedup 1.0000x reference)
#include <cuda_runtime.h>
#include <cuda_bf16.h>
#include <cuda_fp16.h>
#include <cstdint>

// Problem constants
#define NN 20000
#define TT 8
#define FIN 64
#define HEADS 4
#define FILT 32
#define HID 128
#define EE 320000
#define ETOT 340000      // E + N self loops
#define MROWS 160000     // N*T

// ---------------- device scratch ----------------
__device__ __half g_h16[(size_t)MROWS * HID];  // post-GEMM h (fp16, gather source)
__device__ __half g_a16[(size_t)MROWS * HID];  // agg output (fp16, next GEMM A)
__device__ __half g_x16[(size_t)MROWS * FIN];  // x (fp16, permuted)
__device__ __half g_w1[HID * FIN];
__device__ __half g_w2[HID * HID];
__device__ __half g_w3[FILT * HID];
__device__ float  g_es[(size_t)MROWS * HEADS];
__device__ float  g_ed[(size_t)MROWS * HEADS];
__device__ int    g_deg[NN];
__device__ int    g_ticket;
__device__ int    g_rowptr[NN + 1];
__device__ int    g_cursor[NN];
__device__ int    g_csrc[ETOT];

// ---------------- prep: fp16 weights + fp16/permute x (no deg zeroing) -----
__global__ __launch_bounds__(256) void prep_kernel(
    const float* __restrict__ x,
    const float* __restrict__ W1, const float* __restrict__ W2,
    const float* __restrict__ lw1)
{
    int gid = blockIdx.x * 256 + threadIdx.x;

    const int N1 = HID * FIN, N2 = HID * HID, N3 = FILT * HID;
    if (gid < N1) {
        g_w1[gid] = __float2half_rn(W1[gid]);
    } else if (gid < N1 + N2) {
        int j = gid - N1;
        g_w2[j] = __float2half_rn(W2[j]);
    } else if (gid < N1 + N2 + N3) {
        int j = gid - N1 - N2;
        g_w3[j] = __float2half_rn(lw1[j]);
    }

    // x convert + permute: dest row m = t*NN + n  <-  x[n][t][:]
    int w = blockIdx.x * 8 + (threadIdx.x >> 5);   // grid sized to MROWS/8
    int lane = threadIdx.x & 31;
    int t = w / NN, n = w - t * NN;
    float2 v = *(const float2*)(x + ((size_t)n * TT + t) * FIN + lane * 2);
    *(__half2*)(g_x16 + (size_t)w * FIN + lane * 2) = __floats2half2_rn(v.x, v.y);
}

// ---------------- CSR build: count + scan (fused, last-block scans) --------
__global__ __launch_bounds__(1024) void count_scan_kernel(const int* __restrict__ ei) {
    int idx = blockIdx.x * 1024 + threadIdx.x;
    if (idx < ETOT) {
        int dst = (idx < EE) ? ei[EE + idx] : (idx - EE);
        atomicAdd(&g_deg[dst], 1);
    }
    __threadfence();
    __shared__ bool last;
    if (threadIdx.x == 0)
        last = (atomicAdd(&g_ticket, 1) == (int)gridDim.x - 1);
    __syncthreads();
    if (!last) return;

    __shared__ int sh[1024];
    __shared__ int carry;
    if (threadIdx.x == 0) carry = 0;
    __syncthreads();
    for (int base = 0; base < NN; base += 1024) {
        int i = base + threadIdx.x;
        int v = (i < NN) ? g_deg[i] : 0;
        sh[threadIdx.x] = v;
        __syncthreads();
        for (int off = 1; off < 1024; off <<= 1) {
            int t = (threadIdx.x >= off) ? sh[threadIdx.x - off] : 0;
            __syncthreads();
            sh[threadIdx.x] += t;
            __syncthreads();
        }
        int excl = sh[threadIdx.x] - v + carry;
        if (i < NN) { g_rowptr[i] = excl; g_cursor[i] = excl; }
        __syncthreads();
        if (threadIdx.x == 1023) carry += sh[1023];
        __syncthreads();
    }
    if (threadIdx.x == 0) g_rowptr[NN] = ETOT;
}

__global__ void scatter_kernel(const int* __restrict__ ei) {
    int idx = blockIdx.x * blockDim.x + threadIdx.x;
    if (idx >= ETOT) return;
    int src = (idx < EE) ? ei[idx] : (idx - EE);
    int dst = (idx < EE) ? ei[EE + idx] : (idx - EE);
    int p = atomicAdd(&g_cursor[dst], 1);
    g_csrc[p] = src;
}

// ------- fp16 GEMM: MT m-tiles per block, B resident, A 3-stage pipeline ---
// C[M x BN] = A[M x K] * B[BN x K]^T, fp16 in, fp32 accumulate.
// Block: MT tiles x 64 rows, 256 thr, 8 warps = 2(m) x 4(n).
// B panel loaded ONCE per block (shared across tiles) -> staging traffic /MT.
// ESED (BN=128): warp's 32 cols == one head -> emit es/ed + store C (fp16).
// FINAL (BN=32): relu(bias+C) dot lw2 + lb2 -> fout, no C store.

#define MMA_F16(d, a0, a1, a2, a3, b0, b1)                                   \
    asm volatile(                                                            \
        "mma.sync.aligned.m16n8k16.row.col.f32.f16.f16.f32 "                 \
        "{%0,%1,%2,%3}, {%4,%5,%6,%7}, {%8,%9}, {%0,%1,%2,%3};"              \
        : "+f"(d[0]), "+f"(d[1]), "+f"(d[2]), "+f"(d[3])                     \
        : "r"(a0), "r"(a1), "r"(a2), "r"(a3), "r"(b0), "r"(b1))

#define LDSM_X4(r0, r1, r2, r3, addr)                                        \
    asm volatile(                                                            \
        "ldmatrix.sync.aligned.m8n8.x4.shared.b16 {%0,%1,%2,%3}, [%4];"      \
        : "=r"(r0), "=r"(r1), "=r"(r2), "=r"(r3) : "r"(addr))

#define LDSM_X2(r0, r1, addr)                                                \
    asm volatile(                                                            \
        "ldmatrix.sync.aligned.m8n8.x2.shared.b16 {%0,%1}, [%2];"            \
        : "=r"(r0), "=r"(r1) : "r"(addr))

__device__ __forceinline__ void cpa16(void* s, const void* g) {
    uint32_t sa = (uint32_t)__cvta_generic_to_shared(s);
    asm volatile("cp.async.ca.shared.global [%0], [%1], 16;" :: "r"(sa), "l"(g));
}

template<int BN, int K, int MT, int ESED, int FINAL>
__global__ __launch_bounds__(256, 3) void mma_gemm(
    const __half* __restrict__ A, const __half* __restrict__ B,
    __half* __restrict__ Ch, const float* __restrict__ bias,
    const float* __restrict__ attS, const float* __restrict__ attD,
    const float* __restrict__ lw2, const float* __restrict__ lb2,
    float* __restrict__ fout)
{
    const int BM = 64, BK = 32;
    const int LDKA = BK + 8;                // 80B rows: conflict-free ldmatrix
    const int LDKB = K + 8;                 // odd multiple of 16B: conflict-free
    const int NK = K / BK;
    const int IT = MT * NK;                 // flat (tile, kstep) iterations
    const int BNW = BN / 4;                 // cols per warp
    const int BNT = BNW / 8;                // n8 tiles per warp (4 or 1)

    extern __shared__ __half sm[];
    __half* As = sm;                        // [3][BM][LDKA]
    __half* Bs = sm + 3 * BM * LDKA;        // [BN][LDKB] (resident)
    float*  shp = (float*)(Bs + BN * LDKB); // [MT*BM] (FINAL only)

    int tid = threadIdx.x;
    int lane = tid & 31, w = tid >> 5;
    int wm = w & 1, wn = w >> 1;
    int m0 = blockIdx.x * (MT * BM);
    int g = lane >> 2, c = lane & 3;

    // ldmatrix lane addressing
    int a_row = wm * 32 + (lane & 15);                            // + mh*16
    int a_col = ((lane >> 4) << 3);                               // + kb
    int b_row4 = wn * BNW + ((lane >> 4) << 3) + (lane & 7);      // + np*16
    int b_col4 = (((lane >> 3) & 1) << 3);                        // + k off
    int b_row2 = wn * BNW + (lane & 7);
    int b_col2 = (((lane >> 3) & 1) << 3);                        // lanes 0-15

    if (FINAL && tid < MT * BM) shp[tid] = 0.f;

    auto loadA = [&](int st, int it) {
        int mt = it / NK, kt = it - mt * NK;
        const __half* Ab = A + (size_t)(m0 + mt * BM) * K + kt * BK;
#pragma unroll
        for (int q = tid; q < BM * BK / 8; q += 256) {
            int r = q >> 2, kq = (q & 3) * 8;
            cpa16(As + (st * BM + r) * LDKA + kq, Ab + (size_t)r * K + kq);
        }
        asm volatile("cp.async.commit_group;");
    };

    // prologue: B panel (grouped with A it=0) + A it=1
#pragma unroll
    for (int q = tid; q < BN * K / 8; q += 256) {
        int r = q / (K / 8), kq = (q % (K / 8)) * 8;
        cpa16(Bs + r * LDKB + kq, B + (size_t)r * K + kq);
    }
    loadA(0, 0);
    if (IT > 1) loadA(1, 1);

    float acc[2][BNT][4];
#pragma unroll
    for (int i = 0; i < 2; i++)
#pragma unroll
        for (int j = 0; j < BNT; j++)
#pragma unroll
            for (int q = 0; q < 4; q++) acc[i][j][q] = 0.f;

#pragma unroll
    for (int it = 0; it < IT; it++) {
        int st = it % 3;
        int mt = it / NK, kt = it - mt * NK;
        if (it + 1 < IT) asm volatile("cp.async.wait_group 1;");
        else             asm volatile("cp.async.wait_group 0;");
        __syncthreads();
        if (it + 2 < IT) loadA((it + 2) % 3, it + 2);

#pragma unroll
        for (int ks = 0; ks < 2; ks++) {
            int kb = ks * 16;
            uint32_t a[2][4];
#pragma unroll
            for (int mh = 0; mh < 2; mh++) {
                uint32_t ad = (uint32_t)__cvta_generic_to_shared(
                    As + (st * BM + a_row + mh * 16) * LDKA + kb + a_col);
                LDSM_X4(a[mh][0], a[mh][1], a[mh][2], a[mh][3], ad);
            }
            if constexpr (BNT >= 2) {
#pragma unroll
                for (int np = 0; np < BNT / 2; np++) {
                    uint32_t bf[4];
                    uint32_t bd = (uint32_t)__cvta_generic_to_shared(
                        Bs + (b_row4 + np * 16) * LDKB + kt * BK + kb + b_col4);
                    LDSM_X4(bf[0], bf[1], bf[2], bf[3], bd);
#pragma unroll
                    for (int n2 = 0; n2 < 2; n2++) {
                        int nt = 2 * np + n2;
#pragma unroll
                        for (int mh = 0; mh < 2; mh++)
                            MMA_F16(acc[mh][nt], a[mh][0], a[mh][1], a[mh][2], a[mh][3],
                                    bf[2 * n2], bf[2 * n2 + 1]);
                    }
                }
            } else {
                uint32_t bf[2];
                uint32_t bd = (uint32_t)__cvta_generic_to_shared(
                    Bs + b_row2 * LDKB + kt * BK + kb + b_col2);
                LDSM_X2(bf[0], bf[1], bd);
#pragma unroll
                for (int mh = 0; mh < 2; mh++)
                    MMA_F16(acc[mh][0], a[mh][0], a[mh][1], a[mh][2], a[mh][3],
                            bf[0], bf[1]);
            }
        }

        if (kt == NK - 1) {
            // ----- per-tile epilogue (registers only) -----
            int mb = m0 + mt * BM;
            if constexpr (FINAL) {
                float l2v0 = lw2[wn * BNW + 2 * c], l2v1 = lw2[wn * BNW + 2 * c + 1];
                float bv0 = bias[wn * BNW + 2 * c], bv1 = bias[wn * BNW + 2 * c + 1];
#pragma unroll
                for (int mh = 0; mh < 2; mh++) {
#pragma unroll
                    for (int rh = 0; rh < 2; rh++) {
                        float v0 = fmaxf(acc[mh][0][2 * rh]     + bv0, 0.f);
                        float v1 = fmaxf(acc[mh][0][2 * rh + 1] + bv1, 0.f);
                        float p = v0 * l2v0 + v1 * l2v1;
                        p += __shfl_xor_sync(0xffffffffu, p, 1);
                        p += __shfl_xor_sync(0xffffffffu, p, 2);
                        if (c == 0)
                            atomicAdd(&shp[mt * BM + wm * 32 + mh * 16 + g + 8 * rh], p);
                    }
                }
            } else {
                if constexpr (ESED) {
                    // head == wn (warp's 32 columns are exactly one head)
                    float aS[4][2], aD[4][2];
#pragma unroll
                    for (int nt = 0; nt < 4; nt++) {
                        int c0 = wn * 32 + nt * 8 + 2 * c;
                        aS[nt][0] = attS[c0]; aS[nt][1] = attS[c0 + 1];
                        aD[nt][0] = attD[c0]; aD[nt][1] = attD[c0 + 1];
                    }
#pragma unroll
                    for (int mh = 0; mh < 2; mh++) {
#pragma unroll
                        for (int rh = 0; rh < 2; rh++) {
                            float es = 0.f, ed = 0.f;
#pragma unroll
                            for (int nt = 0; nt < 4; nt++) {
                                float v0 = acc[mh][nt][2 * rh], v1 = acc[mh][nt][2 * rh + 1];
                                es += v0 * aS[nt][0] + v1 * aS[nt][1];
                                ed += v0 * aD[nt][0] + v1 * aD[nt][1];
                            }
                            es += __shfl_xor_sync(0xffffffffu, es, 1);
                            es += __shfl_xor_sync(0xffffffffu, es, 2);
                            ed += __shfl_xor_sync(0xffffffffu, ed, 1);
                            ed += __shfl_xor_sync(0xffffffffu, ed, 2);
                            if (c == 0) {
                                int row = mb + wm * 32 + mh * 16 + g + 8 * rh;
                                g_es[(size_t)row * 4 + wn] = es;
                                g_ed[(size_t)row * 4 + wn] = ed;
                            }
                        }
                    }
                }
                // C store (fp16) for gather
#pragma unroll
                for (int mh = 0; mh < 2; mh++) {
                    int r0 = mb + wm * 32 + mh * 16 + g;
#pragma unroll
                    for (int nt = 0; nt < BNT; nt++) {
                        int col = wn * BNW + nt * 8 + 2 * c;
                        *(__half2*)(Ch + (size_t)r0 * BN + col) =
                            __floats2half2_rn(acc[mh][nt][0], acc[mh][nt][1]);
                        *(__half2*)(Ch + (size_t)(r0 + 8) * BN + col) =
                            __floats2half2_rn(acc[mh][nt][2], acc[mh][nt][3]);
                    }
                }
            }
            // reset accumulators for next tile
#pragma unroll
            for (int i = 0; i < 2; i++)
#pragma unroll
                for (int j = 0; j < BNT; j++)
#pragma unroll
                    for (int q = 0; q < 4; q++) acc[i][j][q] = 0.f;
        }
    }

    if constexpr (FINAL) {
        __syncthreads();
        if (tid < MT * BM) fout[m0 + tid] = shp[tid] + lb2[0];
    }
}

// ---------------- aggregation: block = one dst node, warps = 8 time steps --
// All 8 warps share the SAME degree -> zero intra-block straggling.
// Neighbor list staged to smem once per block. Phase A of chunk i+1 is
// software-pipelined ahead of phase B of chunk i (est-chain latency hidden).
// sw layout is the R14 conflict-free [lane] float2 layout.
__global__ __launch_bounds__(256) void agg_kernel(
    const __half* __restrict__ h, const float* __restrict__ bias,
    __half* __restrict__ out16)
{
    __shared__ int    ssrc[256];
    __shared__ float2 sw[8][2][32];
    int d = blockIdx.x;
    int ws = threadIdx.x >> 5;            // warp == time step t
    int lane = threadIdx.x & 31;
    int he = lane & 3, eo = lane >> 2;
    int hf = lane >> 3;
    int beg = g_rowptr[d], end = g_rowptr[d + 1];
    int deg = end - beg;

    // stage neighbor list (shared by all 8 warps)
    for (int i = threadIdx.x; i < deg && i < 256; i += 256)
        ssrc[i] = __ldg(&g_csrc[beg + i]);
    __syncthreads();

    int t = ws;
    size_t w = (size_t)t * NN + d;
    float edv = g_ed[w * 4 + he];
    const __half* ht  = h + (size_t)t * NN * HID;
    const char* htl = (const char*)(ht + lane * 4);
    const float* est = g_es + (size_t)t * NN * 4;

    float s = 0.f;
    float4 acc = make_float4(0.f, 0.f, 0.f, 0.f);

    auto phaseA = [&](int base, int pbuf) {
        int e = base + eo;
        int ec = min(e, deg - 1);
        int src = (ec < 256) ? ssrc[ec] : __ldg(&g_csrc[beg + ec]);
        float ev = __ldg(&est[src * 4 + he]) + edv;
        ev = fmaxf(ev, 0.2f * ev);                    // leaky_relu(0.2)
        float wv = (e < deg) ? __expf(ev) : 0.f;
        s += wv;
        sw[ws][pbuf][lane] = make_float2(wv, __int_as_float(src << 8)); // *256B
    };

    phaseA(0, 0);
    __syncwarp();
    int pb = 0;
    for (int base = 0; base < deg; base += 8, pb ^= 1) {
        if (base + 8 < deg) phaseA(base + 8, pb ^ 1);   // pipelined next chunk
        int nE = deg - base;
        const float2* swp = sw[ws][pb];
#pragma unroll
        for (int j = 0; j < 4; j++) {
            float2 p = swp[j * 4 + hf];
            uint2 hp = *(const uint2*)(htl + __float_as_int(p.y));
            float2 f01 = __half22float2(*(__half2*)&hp.x);
            float2 f23 = __half22float2(*(__half2*)&hp.y);
            acc.x += p.x * f01.x; acc.y += p.x * f01.y;
            acc.z += p.x * f23.x; acc.w += p.x * f23.y;
        }
        if (nE > 4) {
#pragma unroll
            for (int j = 4; j < 8; j++) {
                float2 p = swp[j * 4 + hf];
                uint2 hp = *(const uint2*)(htl + __float_as_int(p.y));
                float2 f01 = __half22float2(*(__half2*)&hp.x);
                float2 f23 = __half22float2(*(__half2*)&hp.y);
                acc.x += p.x * f01.x; acc.y += p.x * f01.y;
                acc.z += p.x * f23.x; acc.w += p.x * f23.y;
            }
        }
        __syncwarp();   // A(i+1) writes visible before B(i+1) reads
    }
    s += __shfl_xor_sync(0xffffffffu, s, 4);
    s += __shfl_xor_sync(0xffffffffu, s, 8);
    s += __shfl_xor_sync(0xffffffffu, s, 16);
    float sAll = __shfl_sync(0xffffffffu, s, hf);

    float inv = 1.f / (sAll + 1e-16f);
    float4 b4 = *(const float4*)(bias + lane * 4);
    float ox = acc.x * inv + b4.x;
    float oy = acc.y * inv + b4.y;
    float oz = acc.z * inv + b4.z;
    float ow = acc.w * inv + b4.w;
    ox = ox > 0.f ? ox : (__expf(ox) - 1.f);
    oy = oy > 0.f ? oy : (__expf(oy) - 1.f);
    oz = oz > 0.f ? oz : (__expf(oz) - 1.f);
    ow = ow > 0.f ? ow : (__expf(ow) - 1.f);

    size_t off = w * HID + lane * 4;
    *(__half2*)(out16 + off)     = __floats2half2_rn(ox, oy);
    *(__half2*)(out16 + off + 2) = __floats2half2_rn(oz, ow);
}

// ---------------- launch ----------------
extern "C" void kernel_launch(void* const* d_in, const int* in_sizes, int n_in,
                              void* d_out, int out_size) {
    const float* x        = (const float*)d_in[0];
    const int*   ei       = (const int*)d_in[1];
    const float* W1       = (const float*)d_in[2];
    const float* att_src1 = (const float*)d_in[3];
    const float* att_dst1 = (const float*)d_in[4];
    const float* b1       = (const float*)d_in[5];
    const float* W2       = (const float*)d_in[6];
    const float* att_src2 = (const float*)d_in[7];
    const float* att_dst2 = (const float*)d_in[8];
    const float* b2       = (const float*)d_in[9];
    const float* lw1      = (const float*)d_in[10];
    const float* lb1      = (const float*)d_in[11];
    const float* lw2      = (const float*)d_in[12];
    const float* lb2      = (const float*)d_in[13];
    float* out = (float*)d_out;

    __half *h16, *a16, *x16, *w1, *w2, *w3;
    void *degp, *tickp;
    cudaGetSymbolAddress((void**)&h16, g_h16);
    cudaGetSymbolAddress((void**)&a16, g_a16);
    cudaGetSymbolAddress((void**)&x16, g_x16);
    cudaGetSymbolAddress((void**)&w1,  g_w1);
    cudaGetSymbolAddress((void**)&w2,  g_w2);
    cudaGetSymbolAddress((void**)&w3,  g_w3);
    cudaGetSymbolAddress(&degp,  g_deg);
    cudaGetSymbolAddress(&tickp, g_ticket);

    const int MT = 2;
    // smem: A 3*64*40*2 = 15360; B BN*(K+8)*2; shp MT*64*4 = 512
    const int smem1 = 15360 + 128 * (FIN + 8) * 2 + 512;   // 34304
    const int smem2 = 15360 + 128 * (HID + 8) * 2 + 512;   // 50688
    const int smem3 = 15360 + 32  * (HID + 8) * 2 + 512;   // 24576
    cudaFuncSetAttribute((const void*)mma_gemm<128, FIN, MT, 1, 0>,
                         cudaFuncAttributeMaxDynamicSharedMemorySize, smem1);
    cudaFuncSetAttribute((const void*)mma_gemm<128, HID, MT, 1, 0>,
                         cudaFuncAttributeMaxDynamicSharedMemorySize, smem2);
    cudaFuncSetAttribute((const void*)mma_gemm<32, HID, MT, 0, 1>,
                         cudaFuncAttributeMaxDynamicSharedMemorySize, smem3);

    // fork resources (capture-safe; proven in R12/R14)
    cudaStream_t s2;
    cudaStreamCreateWithFlags(&s2, cudaStreamNonBlocking);
    cudaEvent_t evFork, evJoin;
    cudaEventCreateWithFlags(&evFork, cudaEventDisableTiming);
    cudaEventCreateWithFlags(&evJoin, cudaEventDisableTiming);

    // fork: CSR build (memsets + count_scan + scatter) on s2,
    //       concurrent with prep + gemm1 on the main stream.
    cudaEventRecord(evFork, 0);
    cudaStreamWaitEvent(s2, evFork, 0);
    cudaMemsetAsync(degp, 0, NN * sizeof(int), s2);
    cudaMemsetAsync(tickp, 0, sizeof(int), s2);
    count_scan_kernel<<<(ETOT + 1023) / 1024, 1024, 0, s2>>>(ei);
    scatter_kernel<<<(ETOT + 255) / 256, 256, 0, s2>>>(ei);
    cudaEventRecord(evJoin, s2);

    // main: prep (weights + x) then gemm1
    prep_kernel<<<MROWS / 8, 256>>>(x, W1, W2, lw1);

    dim3 gg(MROWS / (64 * MT));
    mma_gemm<128, FIN, MT, 1, 0><<<gg, 256, smem1>>>(x16, w1, h16, nullptr,
                                                     att_src1, att_dst1,
                                                     nullptr, nullptr, nullptr);

    // join: agg1 needs gemm1 (main) AND the CSR (s2)
    cudaStreamWaitEvent(0, evJoin, 0);
    agg_kernel<<<NN, 256>>>(h16, b1, a16);

    // layer 2
    mma_gemm<128, HID, MT, 1, 0><<<gg, 256, smem2>>>(a16, w2, h16, nullptr,
                                                     att_src2, att_dst2,
                                                     nullptr, nullptr, nullptr);
    agg_kernel<<<NN, 256>>>(h16, b2, a16);

    // MLP head + final dot (fully fused)
    mma_gemm<32, HID, MT, 0, 1><<<gg, 256, smem3>>>(a16, w3, nullptr, lb1,
                                                    nullptr, nullptr, lw2, lb2, out);
}

// round 17
// speedup vs baseline: 1.0809x; 1.0809x over previous
#include <cuda_runtime.h>
#include <cuda_bf16.h>
#include <cuda_fp16.h>
#include <cstdint>

// Problem constants
#define NN 20000
#define TT 8
#define FIN 64
#define HEADS 4
#define FILT 32
#define HID 128
#define EE 320000
#define ETOT 340000      // E + N self loops
#define MROWS 160000     // N*T

// ---------------- device scratch ----------------
__device__ __half g_h16[(size_t)MROWS * HID];  // post-GEMM h (fp16, gather source)
__device__ __half g_a16[(size_t)MROWS * HID];  // agg output (fp16, next GEMM A)
__device__ __half g_x16[(size_t)MROWS * FIN];  // x (fp16, permuted)
__device__ __half g_w1[HID * FIN];
__device__ __half g_w2[HID * HID];
__device__ __half g_w3[FILT * HID];
__device__ float  g_es[(size_t)MROWS * HEADS];
__device__ float  g_ed[(size_t)MROWS * HEADS];
__device__ int    g_deg[NN];
__device__ int    g_ticket;
__device__ int    g_rowptr[NN + 1];
__device__ int    g_cursor[NN];
__device__ int    g_csrc[ETOT];

// ---------------- prep: fp16 weights + fp16/permute x (no deg zeroing) -----
__global__ __launch_bounds__(256) void prep_kernel(
    const float* __restrict__ x,
    const float* __restrict__ W1, const float* __restrict__ W2,
    const float* __restrict__ lw1)
{
    int gid = blockIdx.x * 256 + threadIdx.x;

    const int N1 = HID * FIN, N2 = HID * HID, N3 = FILT * HID;
    if (gid < N1) {
        g_w1[gid] = __float2half_rn(W1[gid]);
    } else if (gid < N1 + N2) {
        int j = gid - N1;
        g_w2[j] = __float2half_rn(W2[j]);
    } else if (gid < N1 + N2 + N3) {
        int j = gid - N1 - N2;
        g_w3[j] = __float2half_rn(lw1[j]);
    }

    // x convert + permute: dest row m = t*NN + n  <-  x[n][t][:]
    int w = blockIdx.x * 8 + (threadIdx.x >> 5);   // grid sized to MROWS/8
    int lane = threadIdx.x & 31;
    int t = w / NN, n = w - t * NN;
    float2 v = *(const float2*)(x + ((size_t)n * TT + t) * FIN + lane * 2);
    *(__half2*)(g_x16 + (size_t)w * FIN + lane * 2) = __floats2half2_rn(v.x, v.y);
}

// ---------------- CSR build: count + scan (fused, last-block scans) --------
__global__ __launch_bounds__(1024) void count_scan_kernel(const int* __restrict__ ei) {
    int idx = blockIdx.x * 1024 + threadIdx.x;
    if (idx < ETOT) {
        int dst = (idx < EE) ? ei[EE + idx] : (idx - EE);
        atomicAdd(&g_deg[dst], 1);
    }
    __threadfence();
    __shared__ bool last;
    if (threadIdx.x == 0)
        last = (atomicAdd(&g_ticket, 1) == (int)gridDim.x - 1);
    __syncthreads();
    if (!last) return;

    __shared__ int sh[1024];
    __shared__ int carry;
    if (threadIdx.x == 0) carry = 0;
    __syncthreads();
    for (int base = 0; base < NN; base += 1024) {
        int i = base + threadIdx.x;
        int v = (i < NN) ? g_deg[i] : 0;
        sh[threadIdx.x] = v;
        __syncthreads();
        for (int off = 1; off < 1024; off <<= 1) {
            int t = (threadIdx.x >= off) ? sh[threadIdx.x - off] : 0;
            __syncthreads();
            sh[threadIdx.x] += t;
            __syncthreads();
        }
        int excl = sh[threadIdx.x] - v + carry;
        if (i < NN) { g_rowptr[i] = excl; g_cursor[i] = excl; }
        __syncthreads();
        if (threadIdx.x == 1023) carry += sh[1023];
        __syncthreads();
    }
    if (threadIdx.x == 0) g_rowptr[NN] = ETOT;
}

__global__ void scatter_kernel(const int* __restrict__ ei) {
    int idx = blockIdx.x * blockDim.x + threadIdx.x;
    if (idx >= ETOT) return;
    int src = (idx < EE) ? ei[idx] : (idx - EE);
    int dst = (idx < EE) ? ei[EE + idx] : (idx - EE);
    int p = atomicAdd(&g_cursor[dst], 1);
    g_csrc[p] = src;
}

// ------- fp16 GEMM: MT m-tiles per block, B resident, A 3-stage pipeline ---
// C[M x BN] = A[M x K] * B[BN x K]^T, fp16 in, fp32 accumulate.
// Block: MT tiles x 64 rows, 256 thr, 8 warps = 2(m) x 4(n).
// B panel loaded ONCE per block (shared across tiles) -> staging traffic /MT.
// ESED (BN=128): warp's 32 cols == one head -> emit es/ed + store C (fp16).
// FINAL (BN=32): relu(bias+C) dot lw2 + lb2 -> fout, no C store.

#define MMA_F16(d, a0, a1, a2, a3, b0, b1)                                   \
    asm volatile(                                                            \
        "mma.sync.aligned.m16n8k16.row.col.f32.f16.f16.f32 "                 \
        "{%0,%1,%2,%3}, {%4,%5,%6,%7}, {%8,%9}, {%0,%1,%2,%3};"              \
        : "+f"(d[0]), "+f"(d[1]), "+f"(d[2]), "+f"(d[3])                     \
        : "r"(a0), "r"(a1), "r"(a2), "r"(a3), "r"(b0), "r"(b1))

#define LDSM_X4(r0, r1, r2, r3, addr)                                        \
    asm volatile(                                                            \
        "ldmatrix.sync.aligned.m8n8.x4.shared.b16 {%0,%1,%2,%3}, [%4];"      \
        : "=r"(r0), "=r"(r1), "=r"(r2), "=r"(r3) : "r"(addr))

#define LDSM_X2(r0, r1, addr)                                                \
    asm volatile(                                                            \
        "ldmatrix.sync.aligned.m8n8.x2.shared.b16 {%0,%1}, [%2];"            \
        : "=r"(r0), "=r"(r1) : "r"(addr))

__device__ __forceinline__ void cpa16(void* s, const void* g) {
    uint32_t sa = (uint32_t)__cvta_generic_to_shared(s);
    asm volatile("cp.async.ca.shared.global [%0], [%1], 16;" :: "r"(sa), "l"(g));
}

template<int BN, int K, int MT, int ESED, int FINAL>
__global__ __launch_bounds__(256, 3) void mma_gemm(
    const __half* __restrict__ A, const __half* __restrict__ B,
    __half* __restrict__ Ch, const float* __restrict__ bias,
    const float* __restrict__ attS, const float* __restrict__ attD,
    const float* __restrict__ lw2, const float* __restrict__ lb2,
    float* __restrict__ fout)
{
    const int BM = 64, BK = 32;
    const int LDKA = BK + 8;                // 80B rows: conflict-free ldmatrix
    const int LDKB = K + 8;                 // odd multiple of 16B: conflict-free
    const int NK = K / BK;
    const int IT = MT * NK;                 // flat (tile, kstep) iterations
    const int BNW = BN / 4;                 // cols per warp
    const int BNT = BNW / 8;                // n8 tiles per warp (4 or 1)

    extern __shared__ __half sm[];
    __half* As = sm;                        // [3][BM][LDKA]
    __half* Bs = sm + 3 * BM * LDKA;        // [BN][LDKB] (resident)
    float*  shp = (float*)(Bs + BN * LDKB); // [MT*BM] (FINAL only)

    int tid = threadIdx.x;
    int lane = tid & 31, w = tid >> 5;
    int wm = w & 1, wn = w >> 1;
    int m0 = blockIdx.x * (MT * BM);
    int g = lane >> 2, c = lane & 3;

    // ldmatrix lane addressing
    int a_row = wm * 32 + (lane & 15);                            // + mh*16
    int a_col = ((lane >> 4) << 3);                               // + kb
    int b_row4 = wn * BNW + ((lane >> 4) << 3) + (lane & 7);      // + np*16
    int b_col4 = (((lane >> 3) & 1) << 3);                        // + k off
    int b_row2 = wn * BNW + (lane & 7);
    int b_col2 = (((lane >> 3) & 1) << 3);                        // lanes 0-15

    if (FINAL && tid < MT * BM) shp[tid] = 0.f;

    auto loadA = [&](int st, int it) {
        int mt = it / NK, kt = it - mt * NK;
        const __half* Ab = A + (size_t)(m0 + mt * BM) * K + kt * BK;
#pragma unroll
        for (int q = tid; q < BM * BK / 8; q += 256) {
            int r = q >> 2, kq = (q & 3) * 8;
            cpa16(As + (st * BM + r) * LDKA + kq, Ab + (size_t)r * K + kq);
        }
        asm volatile("cp.async.commit_group;");
    };

    // prologue: B panel (grouped with A it=0) + A it=1
#pragma unroll
    for (int q = tid; q < BN * K / 8; q += 256) {
        int r = q / (K / 8), kq = (q % (K / 8)) * 8;
        cpa16(Bs + r * LDKB + kq, B + (size_t)r * K + kq);
    }
    loadA(0, 0);
    if (IT > 1) loadA(1, 1);

    float acc[2][BNT][4];
#pragma unroll
    for (int i = 0; i < 2; i++)
#pragma unroll
        for (int j = 0; j < BNT; j++)
#pragma unroll
            for (int q = 0; q < 4; q++) acc[i][j][q] = 0.f;

#pragma unroll
    for (int it = 0; it < IT; it++) {
        int st = it % 3;
        int mt = it / NK, kt = it - mt * NK;
        if (it + 1 < IT) asm volatile("cp.async.wait_group 1;");
        else             asm volatile("cp.async.wait_group 0;");
        __syncthreads();
        if (it + 2 < IT) loadA((it + 2) % 3, it + 2);

#pragma unroll
        for (int ks = 0; ks < 2; ks++) {
            int kb = ks * 16;
            uint32_t a[2][4];
#pragma unroll
            for (int mh = 0; mh < 2; mh++) {
                uint32_t ad = (uint32_t)__cvta_generic_to_shared(
                    As + (st * BM + a_row + mh * 16) * LDKA + kb + a_col);
                LDSM_X4(a[mh][0], a[mh][1], a[mh][2], a[mh][3], ad);
            }
            if constexpr (BNT >= 2) {
#pragma unroll
                for (int np = 0; np < BNT / 2; np++) {
                    uint32_t bf[4];
                    uint32_t bd = (uint32_t)__cvta_generic_to_shared(
                        Bs + (b_row4 + np * 16) * LDKB + kt * BK + kb + b_col4);
                    LDSM_X4(bf[0], bf[1], bf[2], bf[3], bd);
#pragma unroll
                    for (int n2 = 0; n2 < 2; n2++) {
                        int nt = 2 * np + n2;
#pragma unroll
                        for (int mh = 0; mh < 2; mh++)
                            MMA_F16(acc[mh][nt], a[mh][0], a[mh][1], a[mh][2], a[mh][3],
                                    bf[2 * n2], bf[2 * n2 + 1]);
                    }
                }
            } else {
                uint32_t bf[2];
                uint32_t bd = (uint32_t)__cvta_generic_to_shared(
                    Bs + b_row2 * LDKB + kt * BK + kb + b_col2);
                LDSM_X2(bf[0], bf[1], bd);
#pragma unroll
                for (int mh = 0; mh < 2; mh++)
                    MMA_F16(acc[mh][0], a[mh][0], a[mh][1], a[mh][2], a[mh][3],
                            bf[0], bf[1]);
            }
        }

        if (kt == NK - 1) {
            // ----- per-tile epilogue (registers only) -----
            int mb = m0 + mt * BM;
            if constexpr (FINAL) {
                float l2v0 = lw2[wn * BNW + 2 * c], l2v1 = lw2[wn * BNW + 2 * c + 1];
                float bv0 = bias[wn * BNW + 2 * c], bv1 = bias[wn * BNW + 2 * c + 1];
#pragma unroll
                for (int mh = 0; mh < 2; mh++) {
#pragma unroll
                    for (int rh = 0; rh < 2; rh++) {
                        float v0 = fmaxf(acc[mh][0][2 * rh]     + bv0, 0.f);
                        float v1 = fmaxf(acc[mh][0][2 * rh + 1] + bv1, 0.f);
                        float p = v0 * l2v0 + v1 * l2v1;
                        p += __shfl_xor_sync(0xffffffffu, p, 1);
                        p += __shfl_xor_sync(0xffffffffu, p, 2);
                        if (c == 0)
                            atomicAdd(&shp[mt * BM + wm * 32 + mh * 16 + g + 8 * rh], p);
                    }
                }
            } else {
                if constexpr (ESED) {
                    // head == wn (warp's 32 columns are exactly one head)
                    float aS[4][2], aD[4][2];
#pragma unroll
                    for (int nt = 0; nt < 4; nt++) {
                        int c0 = wn * 32 + nt * 8 + 2 * c;
                        aS[nt][0] = attS[c0]; aS[nt][1] = attS[c0 + 1];
                        aD[nt][0] = attD[c0]; aD[nt][1] = attD[c0 + 1];
                    }
#pragma unroll
                    for (int mh = 0; mh < 2; mh++) {
#pragma unroll
                        for (int rh = 0; rh < 2; rh++) {
                            float es = 0.f, ed = 0.f;
#pragma unroll
                            for (int nt = 0; nt < 4; nt++) {
                                float v0 = acc[mh][nt][2 * rh], v1 = acc[mh][nt][2 * rh + 1];
                                es += v0 * aS[nt][0] + v1 * aS[nt][1];
                                ed += v0 * aD[nt][0] + v1 * aD[nt][1];
                            }
                            es += __shfl_xor_sync(0xffffffffu, es, 1);
                            es += __shfl_xor_sync(0xffffffffu, es, 2);
                            ed += __shfl_xor_sync(0xffffffffu, ed, 1);
                            ed += __shfl_xor_sync(0xffffffffu, ed, 2);
                            if (c == 0) {
                                int row = mb + wm * 32 + mh * 16 + g + 8 * rh;
                                g_es[(size_t)row * 4 + wn] = es;
                                g_ed[(size_t)row * 4 + wn] = ed;
                            }
                        }
                    }
                }
                // C store (fp16) for gather
#pragma unroll
                for (int mh = 0; mh < 2; mh++) {
                    int r0 = mb + wm * 32 + mh * 16 + g;
#pragma unroll
                    for (int nt = 0; nt < BNT; nt++) {
                        int col = wn * BNW + nt * 8 + 2 * c;
                        *(__half2*)(Ch + (size_t)r0 * BN + col) =
                            __floats2half2_rn(acc[mh][nt][0], acc[mh][nt][1]);
                        *(__half2*)(Ch + (size_t)(r0 + 8) * BN + col) =
                            __floats2half2_rn(acc[mh][nt][2], acc[mh][nt][3]);
                    }
                }
            }
            // reset accumulators for next tile
#pragma unroll
            for (int i = 0; i < 2; i++)
#pragma unroll
                for (int j = 0; j < BNT; j++)
#pragma unroll
                    for (int q = 0; q < 4; q++) acc[i][j][q] = 0.f;
        }
    }

    if constexpr (FINAL) {
        __syncthreads();
        if (tid < MT * BM) fout[m0 + tid] = shp[tid] + lb2[0];
    }
}

// ---------------- aggregation: block = one dst node, warps = 8 time steps --
// All 8 warps share the SAME degree -> zero intra-block straggling.
// Neighbor list staged to smem once per block (csrc LDG / 8).
__global__ __launch_bounds__(256) void agg_kernel(
    const __half* __restrict__ h, const float* __restrict__ bias,
    __half* __restrict__ out16)
{
    __shared__ int    ssrc[256];
    __shared__ float2 sw[8][2][32];
    int d = blockIdx.x;
    int ws = threadIdx.x >> 5;            // warp == time step t
    int lane = threadIdx.x & 31;
    int he = lane & 3, eo = lane >> 2;
    int hf = lane >> 3;
    int beg = g_rowptr[d], end = g_rowptr[d + 1];
    int deg = end - beg;

    // stage neighbor list (shared by all 8 warps)
    for (int i = threadIdx.x; i < deg && i < 256; i += 256)
        ssrc[i] = __ldg(&g_csrc[beg + i]);
    __syncthreads();

    int t = ws;
    size_t w = (size_t)t * NN + d;
    float edv = g_ed[w * 4 + he];
    const __half* ht  = h + (size_t)t * NN * HID;
    const char* htl = (const char*)(ht + lane * 4);
    const float* est = g_es + (size_t)t * NN * 4;

    float s = 0.f;
    float4 acc = make_float4(0.f, 0.f, 0.f, 0.f);
    int pb = 0;
    for (int base = 0; base < deg; base += 8, pb ^= 1) {
        int e = base + eo;
        int ec = min(e, deg - 1);
        int src = (ec < 256) ? ssrc[ec] : __ldg(&g_csrc[beg + ec]);
        float ev = __ldg(&est[src * 4 + he]) + edv;
        ev = fmaxf(ev, 0.2f * ev);                    // leaky_relu(0.2)
        float wv = (e < deg) ? __expf(ev) : 0.f;
        s += wv;
        sw[ws][pb][lane] = make_float2(wv, __int_as_float(src << 8)); // *256B row
        __syncwarp();
        int nE = deg - base;
#pragma unroll
        for (int j = 0; j < 4; j++) {
            float2 p = sw[ws][pb][j * 4 + hf];
            uint2 hp = *(const uint2*)(htl + __float_as_int(p.y));
            float2 f01 = __half22float2(*(__half2*)&hp.x);
            float2 f23 = __half22float2(*(__half2*)&hp.y);
            acc.x += p.x * f01.x; acc.y += p.x * f01.y;
            acc.z += p.x * f23.x; acc.w += p.x * f23.y;
        }
        if (nE > 4) {
#pragma unroll
            for (int j = 4; j < 8; j++) {
                float2 p = sw[ws][pb][j * 4 + hf];
                uint2 hp = *(const uint2*)(htl + __float_as_int(p.y));
                float2 f01 = __half22float2(*(__half2*)&hp.x);
                float2 f23 = __half22float2(*(__half2*)&hp.y);
                acc.x += p.x * f01.x; acc.y += p.x * f01.y;
                acc.z += p.x * f23.x; acc.w += p.x * f23.y;
            }
        }
    }
    s += __shfl_xor_sync(0xffffffffu, s, 4);
    s += __shfl_xor_sync(0xffffffffu, s, 8);
    s += __shfl_xor_sync(0xffffffffu, s, 16);
    float sAll = __shfl_sync(0xffffffffu, s, hf);

    float inv = 1.f / (sAll + 1e-16f);
    float4 b4 = *(const float4*)(bias + lane * 4);
    float ox = acc.x * inv + b4.x;
    float oy = acc.y * inv + b4.y;
    float oz = acc.z * inv + b4.z;
    float ow = acc.w * inv + b4.w;
    ox = ox > 0.f ? ox : (__expf(ox) - 1.f);
    oy = oy > 0.f ? oy : (__expf(oy) - 1.f);
    oz = oz > 0.f ? oz : (__expf(oz) - 1.f);
    ow = ow > 0.f ? ow : (__expf(ow) - 1.f);

    size_t off = w * HID + lane * 4;
    *(__half2*)(out16 + off)     = __floats2half2_rn(ox, oy);
    *(__half2*)(out16 + off + 2) = __floats2half2_rn(oz, ow);
}

// ---------------- launch ----------------
extern "C" void kernel_launch(void* const* d_in, const int* in_sizes, int n_in,
                              void* d_out, int out_size) {
    const float* x        = (const float*)d_in[0];
    const int*   ei       = (const int*)d_in[1];
    const float* W1       = (const float*)d_in[2];
    const float* att_src1 = (const float*)d_in[3];
    const float* att_dst1 = (const float*)d_in[4];
    const float* b1       = (const float*)d_in[5];
    const float* W2       = (const float*)d_in[6];
    const float* att_src2 = (const float*)d_in[7];
    const float* att_dst2 = (const float*)d_in[8];
    const float* b2       = (const float*)d_in[9];
    const float* lw1      = (const float*)d_in[10];
    const float* lb1      = (const float*)d_in[11];
    const float* lw2      = (const float*)d_in[12];
    const float* lb2      = (const float*)d_in[13];
    float* out = (float*)d_out;

    __half *h16, *a16, *x16, *w1, *w2, *w3;
    void *degp, *tickp;
    cudaGetSymbolAddress((void**)&h16, g_h16);
    cudaGetSymbolAddress((void**)&a16, g_a16);
    cudaGetSymbolAddress((void**)&x16, g_x16);
    cudaGetSymbolAddress((void**)&w1,  g_w1);
    cudaGetSymbolAddress((void**)&w2,  g_w2);
    cudaGetSymbolAddress((void**)&w3,  g_w3);
    cudaGetSymbolAddress(&degp,  g_deg);
    cudaGetSymbolAddress(&tickp, g_ticket);

    const int MT = 2;
    // smem: A 3*64*40*2 = 15360; B BN*(K+8)*2; shp MT*64*4 = 512
    const int smem1 = 15360 + 128 * (FIN + 8) * 2 + 512;   // 34304
    const int smem2 = 15360 + 128 * (HID + 8) * 2 + 512;   // 50688
    const int smem3 = 15360 + 32  * (HID + 8) * 2 + 512;   // 24576
    cudaFuncSetAttribute((const void*)mma_gemm<128, FIN, MT, 1, 0>,
                         cudaFuncAttributeMaxDynamicSharedMemorySize, smem1);
    cudaFuncSetAttribute((const void*)mma_gemm<128, HID, MT, 1, 0>,
                         cudaFuncAttributeMaxDynamicSharedMemorySize, smem2);
    cudaFuncSetAttribute((const void*)mma_gemm<32, HID, MT, 0, 1>,
                         cudaFuncAttributeMaxDynamicSharedMemorySize, smem3);

    // fork resources (capture-safe; proven in R12/R14)
    cudaStream_t s2;
    cudaStreamCreateWithFlags(&s2, cudaStreamNonBlocking);
    cudaEvent_t evFork, evJoin;
    cudaEventCreateWithFlags(&evFork, cudaEventDisableTiming);
    cudaEventCreateWithFlags(&evJoin, cudaEventDisableTiming);

    // fork: CSR build (memsets + count_scan + scatter) on s2,
    //       concurrent with prep + gemm1 on the main stream.
    cudaEventRecord(evFork, 0);
    cudaStreamWaitEvent(s2, evFork, 0);
    cudaMemsetAsync(degp, 0, NN * sizeof(int), s2);
    cudaMemsetAsync(tickp, 0, sizeof(int), s2);
    count_scan_kernel<<<(ETOT + 1023) / 1024, 1024, 0, s2>>>(ei);
    scatter_kernel<<<(ETOT + 255) / 256, 256, 0, s2>>>(ei);
    cudaEventRecord(evJoin, s2);

    // main: prep (weights + x) then gemm1
    prep_kernel<<<MROWS / 8, 256>>>(x, W1, W2, lw1);

    dim3 gg(MROWS / (64 * MT));
    mma_gemm<128, FIN, MT, 1, 0><<<gg, 256, smem1>>>(x16, w1, h16, nullptr,
                                                     att_src1, att_dst1,
                                                     nullptr, nullptr, nullptr);

    // join: agg1 needs gemm1 (main) AND the CSR (s2)
    cudaStreamWaitEvent(0, evJoin, 0);
    agg_kernel<<<NN, 256>>>(h16, b1, a16);

    // layer 2
    mma_gemm<128, HID, MT, 1, 0><<<gg, 256, smem2>>>(a16, w2, h16, nullptr,
                                                     att_src2, att_dst2,
                                                     nullptr, nullptr, nullptr);
    agg_kernel<<<NN, 256>>>(h16, b2, a16);

    // MLP head + final dot (fully fused)
    mma_gemm<32, HID, MT, 0, 1><<<gg, 256, smem3>>>(a16, w3, nullptr, lb1,
                                                    nullptr, nullptr, lw2, lb2, out);
}